// round 15
// baseline (speedup 1.0000x reference)
#include <cuda_runtime.h>
#include <math.h>

#define T_SNAP 4
#define EQ     4096
#define NNODES 8192
#define H      32
#define BCAP   32                // in-edge bucket capacity per (t, node)
#define RC     64                // per-seed reach cap (2-hop worst ~30)
#define HT     16384             // global hash table slots (power of 2)
#define NQ     (T_SNAP * EQ)     // 16384 queries
#define NB     (EQ * 3)          // pooled nodes (GRU batch)
#define QPB    64                // queries per block in k_query (128 threads)

// Scratch (static device globals, zero-initialized; every call restores zeros)
__device__ int    g_bcnt[T_SNAP * NNODES];
__device__ int    g_bsrc[T_SNAP * NNODES * BCAP];
__device__ float  g_tops[NQ * 3];
__device__ int    g_htkey[HT];             // 0 = empty (reset by GRU consumers)
__device__ float4 g_slotv[HT];
__device__ float  g_uh[HT * H];
__device__ int    g_bslot[NB];
__device__ int    g_uniq[NB];
__device__ int    g_uniq_cnt;              // reset by k_gather

__device__ __forceinline__ float fast_sigmoid(float x) {
    return 1.f / (1.f + __expf(-x));
}
__device__ __forceinline__ float fast_tanh(float x) {
    return 2.f / (1.f + __expf(-2.f * x)) - 1.f;
}

__device__ __forceinline__ bool in_list(const int* l, int n, int x) {
    for (int i = 0; i < n; i++)
        if (l[i] == x) return true;
    return false;
}

// ---------------------------------------------------------------------------
// K0: scatter (t, e) -> bucket of srcs at dst
__global__ void __launch_bounds__(256)
k_scat(const int* __restrict__ ei) {
    int idx = blockIdx.x * 256 + threadIdx.x;
    if (idx >= NQ) return;
    int t = idx >> 12;                 // EQ = 4096
    int e = idx & (EQ - 1);
    int src = __ldg(&ei[t * 2 * EQ + e]);
    int dst = __ldg(&ei[t * 2 * EQ + EQ + e]);
    int pos = atomicAdd(&g_bcnt[t * NNODES + dst], 1);
    if (pos < BCAP) g_bsrc[(t * NNODES + dst) * BCAP + pos] = src;
}

// ---------------------------------------------------------------------------
// Level-batched 2-hop BFS: counts prefetched, buckets loaded as int4 vectors.
// R lives in SHARED memory. Returns reach-set size (capped at RC).
__device__ __forceinline__ int bfs2b(int t, int seed, int* R) {
    const int base = t * NNODES;
    R[0] = seed;
    int n = 1;

    // ---- hop 1: seed's bucket ----
    int c0 = __ldg(&g_bcnt[base + seed]);
    if (c0 > BCAP) c0 = BCAP;
    if (c0 > 0) {
        int buf[BCAP];
        const int4* bp = (const int4*)&g_bsrc[(base + seed) * BCAP];
        int nch = (c0 + 3) >> 2;
        for (int j4 = 0; j4 < nch; j4++) {          // independent vector loads
            int4 vv = __ldg(&bp[j4]);
            buf[j4 * 4 + 0] = vv.x; buf[j4 * 4 + 1] = vv.y;
            buf[j4 * 4 + 2] = vv.z; buf[j4 * 4 + 3] = vv.w;
        }
        for (int j = 0; j < c0; j++) {
            int s = buf[j];
            bool dup = (s == seed);
            for (int i = 1; i < n && !dup; i++) dup = (R[i] == s);
            if (!dup && n < RC) R[n++] = s;
        }
    }
    int e1 = n;

    // ---- hop 2: prefetch all level-1 counts (independent), then buckets ----
    int cnts[BCAP + 1];
    for (int i = 1; i < e1; i++) {
        int c = __ldg(&g_bcnt[base + R[i]]);
        cnts[i] = (c > BCAP) ? BCAP : c;
    }
    for (int i = 1; i < e1; i++) {
        int c = cnts[i];
        if (c == 0) continue;
        int buf[BCAP];
        const int4* bp = (const int4*)&g_bsrc[(base + R[i]) * BCAP];
        int nch = (c + 3) >> 2;
        for (int j4 = 0; j4 < nch; j4++) {
            int4 vv = __ldg(&bp[j4]);
            buf[j4 * 4 + 0] = vv.x; buf[j4 * 4 + 1] = vv.y;
            buf[j4 * 4 + 2] = vv.z; buf[j4 * 4 + 3] = vv.w;
        }
        for (int j = 0; j < c; j++) {
            int s = buf[j];
            bool dup = false;
            for (int k = 0; k < n; k++)
                if (R[k] == s) { dup = true; break; }
            if (!dup && n < RC) R[n++] = s;
        }
    }
    return n;
}

// ---------------------------------------------------------------------------
// K1: 2 threads per query. Even lane: BFS(u) + inclusion over Ru-nodes.
//     Odd lane:  BFS(v) + inclusion over Rv-only nodes. Top-3 merged by shfl.
__global__ void __launch_bounds__(128)
k_query(const int* __restrict__ ei) {
    __shared__ int sR[QPB][2 * RC];

    int tid  = threadIdx.x;
    int qp   = tid >> 1;                       // query slot in block
    int side = tid & 1;                        // 0 = u, 1 = v
    int qi   = blockIdx.x * QPB + qp;          // grid sized exactly: no bounds
    int t    = qi >> 12;
    int q    = qi & (EQ - 1);
    const int base = t * NNODES;

    int seed = __ldg(&ei[(T_SNAP - 1) * 2 * EQ + side * EQ + q]);
    int* Rmine = &sR[qp][side * RC];
    int n = bfs2b(t, seed, Rmine);

    int n_other = __shfl_xor_sync(0xffffffffu, n, 1);
    __syncwarp();                              // partner's shared list visible

    int* Ru = &sR[qp][0];
    int* Rv = &sR[qp][RC];
    int nu = side ? n_other : n;
    int nv = side ? n : n_other;

    float t0 = 0.f, t1 = 0.f, t2 = 0.f;
#define TOP3(f) { if ((f) > t0) { t2 = t1; t1 = t0; t0 = (f); } \
                  else if ((f) > t1) { t2 = t1; t1 = (f); } \
                  else if ((f) > t2) { t2 = (f); } }

    if (side == 0) {
        // nodes reached from u (inRu always true)
        int cn[RC];
        for (int i = 0; i < nu; i++) {          // independent count prefetch
            int c = __ldg(&g_bcnt[base + Ru[i]]);
            cn[i] = (c > BCAP) ? BCAP : c;
        }
        for (int i = 0; i < nu; i++) {
            int node = Ru[i];
            bool inRv = in_list(Rv, nv, node);
            int c = cn[i];
            int d = 0;
            if (c > 0) {
                int buf[BCAP];
                const int4* bp = (const int4*)&g_bsrc[(base + node) * BCAP];
                int nch = (c + 3) >> 2;
                for (int j4 = 0; j4 < nch; j4++) {
                    int4 vv = __ldg(&bp[j4]);
                    buf[j4 * 4 + 0] = vv.x; buf[j4 * 4 + 1] = vv.y;
                    buf[j4 * 4 + 2] = vv.z; buf[j4 * 4 + 3] = vv.w;
                }
                for (int j = 0; j < c; j++) {
                    int s = buf[j];
                    bool ok = in_list(Ru, nu, s) || (inRv && in_list(Rv, nv, s));
                    d += ok;
                }
            }
            TOP3((float)d);
        }
    } else {
        // nodes reached only from v
        int cn[RC];
        for (int i = 0; i < nv; i++) {
            int c = __ldg(&g_bcnt[base + Rv[i]]);
            cn[i] = (c > BCAP) ? BCAP : c;
        }
        for (int i = 0; i < nv; i++) {
            int node = Rv[i];
            if (in_list(Ru, nu, node)) continue;   // handled by even lane
            int c = cn[i];
            int d = 0;
            if (c > 0) {
                int buf[BCAP];
                const int4* bp = (const int4*)&g_bsrc[(base + node) * BCAP];
                int nch = (c + 3) >> 2;
                for (int j4 = 0; j4 < nch; j4++) {
                    int4 vv = __ldg(&bp[j4]);
                    buf[j4 * 4 + 0] = vv.x; buf[j4 * 4 + 1] = vv.y;
                    buf[j4 * 4 + 2] = vv.z; buf[j4 * 4 + 3] = vv.w;
                }
                for (int j = 0; j < c; j++) {
                    int s = buf[j];
                    d += in_list(Rv, nv, s);
                }
            }
            TOP3((float)d);
        }
    }

    // merge the pair's top-3 triples
    float o0 = __shfl_xor_sync(0xffffffffu, t0, 1);
    float o1 = __shfl_xor_sync(0xffffffffu, t1, 1);
    float o2 = __shfl_xor_sync(0xffffffffu, t2, 1);
    TOP3(o0); TOP3(o1); TOP3(o2);
#undef TOP3

    if (side == 0) {
        g_tops[qi * 3 + 0] = t0;
        g_tops[qi * 3 + 1] = t1;
        g_tops[qi * 3 + 2] = t2;
    }
}

// ---------------------------------------------------------------------------
// K2: hierarchical dedup (block SMEM hash -> global, reps only) + bcnt clear
__global__ void __launch_bounds__(256)
k_dedup() {
    __shared__ int skey[512];      // block-level table: 0 = empty (<=256 keys)
    __shared__ int sslot[512];

    int tid = threadIdx.x;
    int idx = blockIdx.x * 256 + tid;    // == b (48*256 == NB)

    // clear bucket counters for next call (k_query already consumed them)
    for (int i = idx; i < T_SNAP * NNODES; i += NB) g_bcnt[i] = 0;

    for (int i = tid; i < 512; i += 256) skey[i] = 0;
    __syncthreads();

    int b = idx;
    int q = b / 3, p = b - q * 3;
    float v0 = g_tops[(0 * EQ + q) * 3 + p];
    float v1 = g_tops[(1 * EQ + q) * 3 + p];
    float v2 = g_tops[(2 * EQ + q) * 3 + p];
    float v3 = g_tops[(3 * EQ + q) * 3 + p];
    // degrees <= BCAP = 32: always packable; tag bit keeps key nonzero
    int key = (int)v0 | ((int)v1 << 8) | ((int)v2 << 16) | ((int)v3 << 24)
            | 0x40000000;

    unsigned hb = ((unsigned)key * 2654435761u >> 14) & 511u;
    int bi;
    bool rep = false;
    for (;;) {
        int old = atomicCAS(&skey[hb], 0, key);
        if (old == 0)  { rep = true; bi = (int)hb; break; }
        if (old == key) { bi = (int)hb; break; }
        hb = (hb + 1) & 511u;
    }

    if (rep) {
        unsigned hg = ((unsigned)key * 2654435761u) & (HT - 1);
        int slot;
        for (;;) {
            int cur = ((volatile int*)g_htkey)[hg];
            if (cur == key) { slot = (int)hg; break; }
            if (cur == 0) {
                int old = atomicCAS(&g_htkey[hg], 0, key);
                if (old == 0) {
                    g_slotv[hg] = make_float4(v0, v1, v2, v3);
                    int u = atomicAdd(&g_uniq_cnt, 1);
                    g_uniq[u] = (int)hg;
                    slot = (int)hg;
                    break;
                }
                if (old == key) { slot = (int)hg; break; }
            }
            hg = (hg + 1) & (HT - 1);
        }
        sslot[bi] = slot;
    }
    __syncthreads();
    g_bslot[b] = sslot[bi];
}

// ---------------------------------------------------------------------------
// K3: warp-per-unique GRU; gi(v<=32) table in SMEM; resets consumed slots
__global__ void __launch_bounds__(128)
k_gru(const float* __restrict__ Wg,  const float* __restrict__ bg,
      const float* __restrict__ Wih, const float* __restrict__ Whh,
      const float* __restrict__ bih, const float* __restrict__ bhh) {
    __shared__ float sWih[3 * H * H];      // [j*H + kk] (for gi build)
    __shared__ float sWhhT[H][3 * H];      // [kk][j], conflict-free
    __shared__ float sgi[33][3 * H];       // gi(v), degrees 0..32
    __shared__ float sbhh[3 * H];
    __shared__ float sWg[H], sbg[H];

    int tid = threadIdx.x;
    for (int i = tid; i < 3 * H * H; i += 128) {
        sWih[i] = Wih[i];
        int j = i / H, kk = i - j * H;
        sWhhT[kk][j] = Whh[i];
    }
    if (tid < 3 * H) sbhh[tid] = bhh[tid];
    if (tid < H) { sWg[tid] = Wg[tid]; sbg[tid] = bg[tid]; }
    __syncthreads();

    for (int i = tid; i < 33 * 3 * H; i += 128) {
        int v = i / (3 * H);
        int j = i - v * (3 * H);
        float acc = __ldg(&bih[j]);
        float fv = (float)v;
#pragma unroll
        for (int kk = 0; kk < H; kk++) {
            float xk = fmaxf(fv * sWg[kk] + sbg[kk], 0.f);
            acc += sWih[j * H + kk] * xk;
        }
        sgi[v][j] = acc;
    }
    __syncthreads();

    int cnt = g_uniq_cnt;
    int lane = tid & 31;
    int w = blockIdx.x * 4 + (tid >> 5);       // 96 blocks x 4 warps = 384
    for (int u = w; u < cnt; u += 96 * 4) {
        int slot = g_uniq[u];
        float4 vv = g_slotv[slot];
        float vs[4] = {vv.x, vv.y, vv.z, vv.w};

        float pr[4], pz[4], pg[4];
#pragma unroll
        for (int t = 0; t < T_SNAP; t++) {
            const float* gp = sgi[(int)vs[t]];     // degree <= 32 always
            pr[t] = gp[lane];
            pz[t] = gp[H + lane];
            pg[t] = gp[2 * H + lane];
        }

        float h = 0.f;
#pragma unroll
        for (int t = 0; t < T_SNAP; t++) {
            float hr = sbhh[lane], hz = sbhh[H + lane], hg = sbhh[2 * H + lane];
#pragma unroll
            for (int kk = 0; kk < H; kk++) {
                float hk = __shfl_sync(0xffffffffu, h, kk);
                hr += sWhhT[kk][lane]         * hk;
                hz += sWhhT[kk][H + lane]     * hk;
                hg += sWhhT[kk][2 * H + lane] * hk;
            }
            float r = fast_sigmoid(pr[t] + hr);
            float z = fast_sigmoid(pz[t] + hz);
            float n = fast_tanh(pg[t] + r * hg);
            h = (1.f - z) * n + z * h;
        }
        g_uh[slot * H + lane] = h;
        if (lane == 0) g_htkey[slot] = 0;   // reset consumed slot for next call
    }
}

// ---------------------------------------------------------------------------
// K4: parallel coalesced gather to output + uniq counter reset
__global__ void __launch_bounds__(256)
k_gather(float* __restrict__ out) {
    int i = blockIdx.x * 256 + threadIdx.x;
    if (i == 0) g_uniq_cnt = 0;            // reset for next call
    if (i >= NB * H) return;
    int b = i >> 5;
    int j = i & (H - 1);
    out[i] = g_uh[g_bslot[b] * H + j];
}

// ---------------------------------------------------------------------------
extern "C" void kernel_launch(void* const* d_in, const int* in_sizes, int n_in,
                              void* d_out, int out_size) {
    const int*   ei  = (const int*)d_in[0];
    const float* Wg  = (const float*)d_in[1];
    const float* bg  = (const float*)d_in[2];
    const float* Wih = (const float*)d_in[3];
    const float* Whh = (const float*)d_in[4];
    const float* bih = (const float*)d_in[5];
    const float* bhh = (const float*)d_in[6];
    float* out = (float*)d_out;

    k_scat  <<<NQ / 256, 256>>>(ei);                       // 64 blocks
    k_query <<<NQ * 2 / 128, 128>>>(ei);                   // 256 blocks, 2 thr/query
    k_dedup <<<NB / 256, 256>>>();                         // 48 blocks
    k_gru   <<<96, 128>>>(Wg, bg, Wih, Whh, bih, bhh);     // 384 warps
    k_gather<<<(NB * H) / 256, 256>>>(out);                // 1536 blocks
}

// round 16
// speedup vs baseline: 1.0274x; 1.0274x over previous
#include <cuda_runtime.h>
#include <math.h>

#define T_SNAP 4
#define EQ     4096
#define NNODES 8192
#define H      32
#define BCAP   32                // in-edge bucket capacity per (t, node)
#define LCAP   24                // light-path reach cap (overflow -> heavy queue)
#define RCAP   128               // heavy-path reach capacity (warp, smem)
#define BW     256               // bitmap words per reach set (8192 bits)
#define HT     16384             // global hash table slots (power of 2)
#define NQ     (T_SNAP * EQ)     // 16384 queries
#define NB     (EQ * 3)          // pooled nodes (GRU batch)
#define HQCAP  NQ                // heavy queue capacity (cannot overflow)

#define GRID1  296               // 2 blocks/SM, all-resident (barrier-safe)
#define BLK1   256
#define WPB1   (BLK1 / 32)

#define GRID2  296
#define BLK2   128
#define NTH2   (GRID2 * BLK2)
#define NWARP2 (GRID2 * (BLK2 / 32))

// Scratch (static device globals, zero-initialized; every call restores zeros)
__device__ int    g_bcnt[T_SNAP * NNODES];
__device__ int    g_bsrc[T_SNAP * NNODES * BCAP];
__device__ float  g_tops[NQ * 3];
__device__ float  g_gi[256 * 3 * H];       // gi(v): bih folded in
__device__ int    g_htkey[HT];             // 0 = empty
__device__ float4 g_slotv[HT];
__device__ float  g_uh[HT * H];
__device__ int    g_bslot[NB];
__device__ int    g_uniq[NB];
__device__ int    g_uniq_cnt;
__device__ int    g_hq[HQCAP];             // heavy-query queue
__device__ int    g_hq_cnt, g_hq_tick;     // reset by k_rnn
__device__ int    g_cnt1a, g_cnt1b, g_cnt2, g_cnt3;          // barrier counters
__device__ volatile int g_flag1a, g_flag1b, g_flag2, g_flag3; // barrier flags

__device__ __forceinline__ void gbar(int* cnt, volatile int* flag, int target) {
    __syncthreads();
    if (threadIdx.x == 0) {
        __threadfence();
        if (atomicAdd(cnt, 1) == target - 1) {
            *cnt = 0;
            __threadfence();
            *flag = 1;
        } else {
            while (*flag == 0) {}
        }
        __threadfence();
    }
    __syncthreads();
}

__device__ __forceinline__ float fast_sigmoid(float x) {
    return 1.f / (1.f + __expf(-x));
}
__device__ __forceinline__ float fast_tanh(float x) {
    return 2.f / (1.f + __expf(-2.f * x)) - 1.f;
}

__device__ __forceinline__ bool in_list(const int* l, int n, int x) {
    for (int i = 0; i < n; i++)
        if (l[i] == x) return true;
    return false;
}

__device__ __forceinline__ bool btest(const unsigned* Bm, int x) {
    return (Bm[x >> 5] >> (x & 31)) & 1u;
}

// ---- light path: thread-serial 2-hop BFS capped at LCAP; -1 = overflow ----
__device__ __forceinline__ int bfs2_light(int t, int seed, int* R) {
    R[0] = seed;
    int n = 1, s = 0, e = 1;
#pragma unroll
    for (int hop = 0; hop < 2; hop++) {
        for (int i = s; i < e; i++) {
            int node = R[i];
            int c = g_bcnt[t * NNODES + node];
            if (c > BCAP) c = BCAP;
            const int* b = &g_bsrc[(t * NNODES + node) * BCAP];
            for (int j = 0; j < c; j++) {
                int src = b[j];
                if (!in_list(R, n, src)) {
                    if (n >= LCAP) return -1;      // defer to heavy queue
                    R[n++] = src;
                }
            }
        }
        s = e; e = n;
    }
    return n;
}

// ---- heavy path: warp-parallel BFS with smem bitmap + list (R7, proven) ----
__device__ int warp_bfs(int t, int seed, unsigned* Bm, int* L, int lane) {
    if (lane == 0) {
        L[0] = seed;
        Bm[seed >> 5] |= 1u << (seed & 31);
    }
    __syncwarp();
    int n = 1, s = 0, e = 1;
#pragma unroll
    for (int hop = 0; hop < 2; hop++) {
        for (int i = s; i < e; i++) {
            int node = L[i];
            int c = g_bcnt[t * NNODES + node];
            if (c > BCAP) c = BCAP;
            int src = (lane < c) ? g_bsrc[(t * NNODES + node) * BCAP + lane]
                                 : (0x40000000 | lane);   // unique sentinel
            bool isnew = (lane < c) && !btest(Bm, src);
            unsigned grp = __match_any_sync(0xffffffffu, src);
            unsigned newm = __ballot_sync(0xffffffffu, isnew);
            bool leader = isnew && ((grp & newm & ((1u << lane) - 1u)) == 0);
            unsigned lm = __ballot_sync(0xffffffffu, leader);
            int pos = n + __popc(lm & ((1u << lane) - 1u));
            if (leader && pos < RCAP) {
                L[pos] = src;
                atomicOr(&Bm[src >> 5], 1u << (src & 31));
            }
            n += __popc(lm);
            if (n > RCAP) n = RCAP;
            __syncwarp();
        }
        s = e; e = n;
    }
    return n;
}

__device__ void warp_query(int t, int qi, int u, int v, int lane,
                           unsigned* BmU, unsigned* BmV, int* Lu, int* Lv) {
    for (int w = lane; w < BW; w += 32) { BmU[w] = 0u; BmV[w] = 0u; }
    __syncwarp();
    int nu = warp_bfs(t, u, BmU, Lu, lane);
    int nv = warp_bfs(t, v, BmV, Lv, lane);

    float t0 = 0.f, t1 = 0.f, t2 = 0.f;
    for (int i = 0; i < nu; i++) {
        int node = Lu[i];
        bool nodeInV = btest(BmV, node);
        int c = g_bcnt[t * NNODES + node];
        if (c > BCAP) c = BCAP;
        bool ok = false;
        if (lane < c) {
            int src = g_bsrc[(t * NNODES + node) * BCAP + lane];
            ok = btest(BmU, src) || (nodeInV && btest(BmV, src));
        }
        float f = (float)__popc(__ballot_sync(0xffffffffu, ok));
        if (f > t0)      { t2 = t1; t1 = t0; t0 = f; }
        else if (f > t1) { t2 = t1; t1 = f; }
        else if (f > t2) { t2 = f; }
    }
    for (int i = 0; i < nv; i++) {
        int node = Lv[i];
        if (btest(BmU, node)) continue;         // handled above
        int c = g_bcnt[t * NNODES + node];
        if (c > BCAP) c = BCAP;
        bool ok = false;
        if (lane < c) {
            int src = g_bsrc[(t * NNODES + node) * BCAP + lane];
            ok = btest(BmV, src);
        }
        float f = (float)__popc(__ballot_sync(0xffffffffu, ok));
        if (f > t0)      { t2 = t1; t1 = t0; t0 = f; }
        else if (f > t1) { t2 = t1; t1 = f; }
        else if (f > t2) { t2 = f; }
    }
    if (lane == 0) {
        g_tops[qi * 3 + 0] = t0;
        g_tops[qi * 3 + 1] = t1;
        g_tops[qi * 3 + 2] = t2;
    }
    __syncwarp();
}

// ---------------------------------------------------------------------------
// k1: scatter -> bar -> light queries (heavies enqueued) -> bar
//     -> ticket-balanced warp-cooperative heavy processing
__global__ void __launch_bounds__(BLK1, 2)
k_graph(const int* __restrict__ ei) {
    __shared__ unsigned sBmU[WPB1][BW];
    __shared__ unsigned sBmV[WPB1][BW];
    __shared__ int      sLu[WPB1][RCAP];
    __shared__ int      sLv[WPB1][RCAP];

    int tid = threadIdx.x;
    int idx = blockIdx.x * BLK1 + tid;

    if (idx == 0) { g_uniq_cnt = 0; g_flag2 = 0; g_flag3 = 0; }  // for k2

    // ---- phase A: scatter (t, e) -> bucket of srcs at dst ----
    if (idx < NQ) {
        int t = idx >> 12;             // EQ = 4096
        int e = idx & (EQ - 1);
        int src = __ldg(&ei[t * 2 * EQ + e]);
        int dst = __ldg(&ei[t * 2 * EQ + EQ + e]);
        int pos = atomicAdd(&g_bcnt[t * NNODES + dst], 1);
        if (pos < BCAP) g_bsrc[(t * NNODES + dst) * BCAP + pos] = src;
    }

    gbar(&g_cnt1a, &g_flag1a, GRID1);

    // ---- phase B: light thread-per-query (every 4th lane); enqueue heavies --
    if ((idx & 3) == 0 && (idx >> 2) < NQ) {
        int qi = idx >> 2;
        int t = qi >> 12;
        int q = qi & (EQ - 1);
        int u = __ldg(&ei[(T_SNAP - 1) * 2 * EQ + q]);
        int v = __ldg(&ei[(T_SNAP - 1) * 2 * EQ + EQ + q]);

        int Ru[LCAP], Rv[LCAP];
        int nu = bfs2_light(t, u, Ru);
        int nv = (nu >= 0) ? bfs2_light(t, v, Rv) : -1;

        if (nu < 0 || nv < 0) {
            int pos = atomicAdd(&g_hq_cnt, 1);     // HQCAP == NQ: never overflows
            g_hq[pos] = qi;
        } else {
            float t0 = 0.f, t1 = 0.f, t2 = 0.f;
            for (int pass = 0; pass < 2; pass++) {
                const int* L = pass ? Rv : Ru;
                int nL = pass ? nv : nu;
                for (int i = 0; i < nL; i++) {
                    int node = L[i];
                    bool inRu, inRv;
                    if (pass == 0) {
                        inRu = true;
                        inRv = in_list(Rv, nv, node);
                    } else {
                        inRu = in_list(Ru, nu, node);
                        if (inRu) continue;        // handled in pass 0
                        inRv = true;
                    }
                    int c = g_bcnt[t * NNODES + node];
                    if (c > BCAP) c = BCAP;
                    const int* b = &g_bsrc[(t * NNODES + node) * BCAP];
                    int d = 0;
                    for (int j = 0; j < c; j++) {
                        int src = b[j];
                        bool su = inRu && in_list(Ru, nu, src);
                        bool sv = inRv && in_list(Rv, nv, src);
                        if (su || sv) d++;
                    }
                    float f = (float)d;
                    if (f > t0)      { t2 = t1; t1 = t0; t0 = f; }
                    else if (f > t1) { t2 = t1; t1 = f; }
                    else if (f > t2) { t2 = f; }
                }
            }
            g_tops[qi * 3 + 0] = t0;
            g_tops[qi * 3 + 1] = t1;
            g_tops[qi * 3 + 2] = t2;
        }
    }

    gbar(&g_cnt1b, &g_flag1b, GRID1);

    // ---- phase C: warps pull heavy queries from the global ticket queue ----
    int lane = tid & 31;
    int wp   = tid >> 5;
    int hcnt = g_hq_cnt;
    for (;;) {
        int tk = 0;
        if (lane == 0) tk = atomicAdd(&g_hq_tick, 1);
        tk = __shfl_sync(0xffffffffu, tk, 0);
        if (tk >= hcnt) break;
        int hqi = g_hq[tk];
        int t = hqi >> 12;
        int q = hqi & (EQ - 1);
        int u = __ldg(&ei[(T_SNAP - 1) * 2 * EQ + q]);
        int v = __ldg(&ei[(T_SNAP - 1) * 2 * EQ + EQ + q]);
        warp_query(t, hqi, u, v, lane, sBmU[wp], sBmV[wp], sLu[wp], sLv[wp]);
    }
}

// ---------------------------------------------------------------------------
// k2 (R6 verbatim): gi table + 2-level dedup -> bar -> GRU -> bar -> gather
__global__ void __launch_bounds__(BLK2, 2)
k_rnn(const float* __restrict__ Wg,  const float* __restrict__ bg,
      const float* __restrict__ Wih, const float* __restrict__ Whh,
      const float* __restrict__ bih, const float* __restrict__ bhh,
      float* __restrict__ out) {
    __shared__ float sWihT[H][3 * H];   // [kk][j], conflict-free
    __shared__ float sWhhT[H][3 * H];
    __shared__ float sbhh[3 * H];
    __shared__ float sWg[H], sbg[H];
    __shared__ int   bkey[256];         // block-level dedup table
    __shared__ int   bval[256];

    int tid = threadIdx.x;
    int idx = blockIdx.x * BLK2 + tid;

    if (idx == 0) {                     // resets for next call's k1
        g_flag1a = 0; g_flag1b = 0;
        g_hq_cnt = 0; g_hq_tick = 0;
    }

    for (int i = tid; i < 3 * H * H; i += BLK2) {
        int j = i / H, kk = i - j * H;
        sWihT[kk][j] = Wih[i];
        sWhhT[kk][j] = Whh[i];
    }
    if (tid < 3 * H) sbhh[tid] = bhh[tid];
    if (tid < H) { sWg[tid] = Wg[tid]; sbg[tid] = bg[tid]; }
    for (int i = tid; i < 256; i += BLK2) bkey[i] = 0;
    __syncthreads();

    // ---- phase A1: gi(v) table ----
    if (idx < 256 * 3 * H) {
        int v = idx / (3 * H);
        int j = idx - v * (3 * H);
        float acc = __ldg(&bih[j]);
        float fv = (float)v;
#pragma unroll
        for (int kk = 0; kk < H; kk++) {
            float xk = fmaxf(fv * sWg[kk] + sbg[kk], 0.f);
            acc += sWihT[kk][j] * xk;
        }
        g_gi[idx] = acc;
    }

    // ---- phase A2: two-level dedup of degree 4-tuples ----
    int  bi = -1;
    bool rep = false;
    int  key = 0;
    float v0 = 0.f, v1 = 0.f, v2 = 0.f, v3 = 0.f;
    if (idx < NB) {
        int b = idx;
        int q = b / 3, p = b - q * 3;
        v0 = g_tops[(0 * EQ + q) * 3 + p];
        v1 = g_tops[(1 * EQ + q) * 3 + p];
        v2 = g_tops[(2 * EQ + q) * 3 + p];
        v3 = g_tops[(3 * EQ + q) * 3 + p];
        int i0 = (int)v0, i1 = (int)v1, i2 = (int)v2, i3 = (int)v3;
        if (i0 > 254 || i1 > 254 || i2 > 254 || i3 > 254)
            key = (int)(0x80000000u | (unsigned)b);        // unique-self
        else
            key = i0 | (i1 << 8) | (i2 << 16) | (i3 << 24) | 0x40000000;
        unsigned p2 = ((unsigned)key * 2654435761u) & 255u;
        for (;;) {
            int old = atomicCAS(&bkey[p2], 0, key);
            if (old == 0)  { rep = true; bi = (int)p2; break; }
            if (old == key) { bi = (int)p2; break; }
            p2 = (p2 + 1) & 255u;
        }
    }
    __syncthreads();
    if (rep) {
        unsigned hsl = ((unsigned)key * 2654435761u) & (HT - 1);
        int slot;
        for (;;) {
            int cur = ((volatile int*)g_htkey)[hsl];
            if (cur == key) { slot = (int)hsl; break; }
            if (cur == 0) {
                int old = atomicCAS(&g_htkey[hsl], 0, key);
                if (old == 0) {
                    g_slotv[hsl] = make_float4(v0, v1, v2, v3);
                    int u = atomicAdd(&g_uniq_cnt, 1);
                    g_uniq[u] = (int)hsl;
                    slot = (int)hsl;
                    break;
                }
                if (old == key) { slot = (int)hsl; break; }
            }
            hsl = (hsl + 1) & (HT - 1);
        }
        bval[bi] = slot;
    }
    __syncthreads();
    if (idx < NB) g_bslot[idx] = bval[bi];

    gbar(&g_cnt2, &g_flag2, GRID2);

    // ---- phase B1: clear bucket counters for next call ----
    for (int i = idx; i < T_SNAP * NNODES; i += NTH2) g_bcnt[i] = 0;

    // ---- phase B2: GRU per unique trajectory (one warp each) ----
    int cnt = g_uniq_cnt;
    int lane = tid & 31;
    int w = blockIdx.x * (BLK2 / 32) + (tid >> 5);
    for (int wg = w; wg < cnt; wg += NWARP2) {
        int slot = g_uniq[wg];
        float4 vv = g_slotv[slot];
        float vs[4] = {vv.x, vv.y, vv.z, vv.w};

        float pr[4], pz[4], pg[4];
#pragma unroll
        for (int t = 0; t < T_SNAP; t++) {
            int iv = (int)vs[t];
            if (iv >= 0 && iv < 256) {
                const float* gp = &g_gi[iv * 3 * H];
                pr[t] = gp[lane];
                pz[t] = gp[H + lane];
                pg[t] = gp[2 * H + lane];
            } else {   // rare exact fallback
                float x = fmaxf(vs[t] * sWg[lane] + sbg[lane], 0.f);
                float ar = __ldg(&bih[lane]);
                float az = __ldg(&bih[H + lane]);
                float ag = __ldg(&bih[2 * H + lane]);
                for (int kk = 0; kk < H; kk++) {
                    float xk = __shfl_sync(0xffffffffu, x, kk);
                    ar += sWihT[kk][lane]         * xk;
                    az += sWihT[kk][H + lane]     * xk;
                    ag += sWihT[kk][2 * H + lane] * xk;
                }
                pr[t] = ar; pz[t] = az; pg[t] = ag;
            }
        }

        float h = 0.f;
#pragma unroll
        for (int t = 0; t < T_SNAP; t++) {
            float hr = sbhh[lane], hz = sbhh[H + lane], hg = sbhh[2 * H + lane];
#pragma unroll
            for (int kk = 0; kk < H; kk++) {
                float hk = __shfl_sync(0xffffffffu, h, kk);
                hr += sWhhT[kk][lane]         * hk;
                hz += sWhhT[kk][H + lane]     * hk;
                hg += sWhhT[kk][2 * H + lane] * hk;
            }
            float r = fast_sigmoid(pr[t] + hr);
            float z = fast_sigmoid(pz[t] + hz);
            float n = fast_tanh(pg[t] + r * hg);
            h = (1.f - z) * n + z * h;
        }
        g_uh[slot * H + lane] = h;
        if (lane == 0) g_htkey[slot] = 0;   // reset for next call
    }

    gbar(&g_cnt3, &g_flag3, GRID2);

    // ---- phase C: parallel coalesced gather to output ----
    for (int i = idx; i < NB * H; i += NTH2) {
        int b = i >> 5;
        int j = i & (H - 1);
        out[i] = g_uh[g_bslot[b] * H + j];
    }
}

// ---------------------------------------------------------------------------
extern "C" void kernel_launch(void* const* d_in, const int* in_sizes, int n_in,
                              void* d_out, int out_size) {
    const int*   ei  = (const int*)d_in[0];
    const float* Wg  = (const float*)d_in[1];
    const float* bg  = (const float*)d_in[2];
    const float* Wih = (const float*)d_in[3];
    const float* Whh = (const float*)d_in[4];
    const float* bih = (const float*)d_in[5];
    const float* bhh = (const float*)d_in[6];
    float* out = (float*)d_out;

    k_graph<<<GRID1, BLK1>>>(ei);
    k_rnn  <<<GRID2, BLK2>>>(Wg, bg, Wih, Whh, bih, bhh, out);
}

// round 17
// speedup vs baseline: 1.1702x; 1.1389x over previous
#include <cuda_runtime.h>
#include <math.h>

#define T_SNAP 4
#define EQ     4096
#define NNODES 8192
#define H      32
#define BCAP   32                // in-edge bucket capacity per (t, node)
#define RCAP   128               // per-query reach-set capacity
#define BWL    256               // local bitmap words (8192 bits)
#define HVY    16                // nu+nv threshold for bitmap fast path
#define HT     16384             // global hash table slots (power of 2)
#define NQ     (T_SNAP * EQ)     // 16384 queries
#define NB     (EQ * 3)          // pooled nodes (GRU batch)

#define GRID1  296               // 2 blocks/SM, all-resident (barrier-safe)
#define BLK1   256

#define GRID2  148               // 1 block/SM: less skew, fewer weight reloads
#define BLK2   128
#define NTH2   (GRID2 * BLK2)
#define NWARP2 (GRID2 * (BLK2 / 32))   // 592 warps >= max uniques (<=384)

// Scratch (static device globals, zero-initialized; every call restores zeros)
__device__ int    g_bcnt[T_SNAP * NNODES];
__device__ int    g_bsrc[T_SNAP * NNODES * BCAP];
__device__ float  g_tops[NQ * 3];
__device__ float  g_gi[256 * 3 * H];       // gi(v): bih folded in
__device__ int    g_htkey[HT];             // 0 = empty
__device__ float4 g_slotv[HT];
__device__ float  g_uh[HT * H];
__device__ int    g_bslot[NB];
__device__ int    g_uniq[NB];
__device__ int    g_uniq_cnt;
__device__ int    g_cnt1, g_cnt2, g_cnt3;          // barrier arrive counters
__device__ volatile int g_flag1, g_flag2, g_flag3; // barrier release flags

__device__ __forceinline__ void gbar(int* cnt, volatile int* flag, int target) {
    __syncthreads();
    if (threadIdx.x == 0) {
        __threadfence();
        if (atomicAdd(cnt, 1) == target - 1) {
            *cnt = 0;
            __threadfence();
            *flag = 1;
        } else {
            while (*flag == 0) {}
        }
        __threadfence();
    }
    __syncthreads();
}

__device__ __forceinline__ float fast_sigmoid(float x) {
    return 1.f / (1.f + __expf(-x));
}
__device__ __forceinline__ float fast_tanh(float x) {
    return 2.f / (1.f + __expf(-2.f * x)) - 1.f;
}

__device__ __forceinline__ bool in_list(const int* l, int n, int x) {
    for (int i = 0; i < n; i++)
        if (l[i] == x) return true;
    return false;
}

// 2-hop backward BFS from seed within snapshot t; returns set size
__device__ __forceinline__ int bfs2(int t, int seed, int* R) {
    R[0] = seed;
    int n = 1, s = 0, e = 1;
#pragma unroll
    for (int hop = 0; hop < 2; hop++) {
        for (int i = s; i < e; i++) {
            int node = R[i];
            int c = g_bcnt[t * NNODES + node];
            if (c > BCAP) c = BCAP;
            const int* b = &g_bsrc[(t * NNODES + node) * BCAP];
            for (int j = 0; j < c; j++) {
                int src = b[j];
                if (!in_list(R, n, src) && n < RCAP) R[n++] = src;
            }
        }
        s = e; e = n;
    }
    return n;
}

__device__ __forceinline__ bool btst(const unsigned* Bm, int x) {
    return (Bm[x >> 5] >> (x & 31)) & 1u;
}

// ---------------------------------------------------------------------------
// k1: scatter -> grid barrier -> thread-per-(t,q) query + top-3
//     (adaptive: heavy queries use local bitmaps for O(1) membership)
__global__ void __launch_bounds__(BLK1, 2)
k_graph(const int* __restrict__ ei) {
    int idx = blockIdx.x * BLK1 + threadIdx.x;

    if (idx == 0) { g_uniq_cnt = 0; g_flag2 = 0; g_flag3 = 0; }  // for k2

    // ---- phase A: scatter (t, e) -> bucket of srcs at dst ----
    if (idx < NQ) {
        int t = idx >> 12;             // EQ = 4096
        int e = idx & (EQ - 1);
        int src = __ldg(&ei[t * 2 * EQ + e]);
        int dst = __ldg(&ei[t * 2 * EQ + EQ + e]);
        int pos = atomicAdd(&g_bcnt[t * NNODES + dst], 1);
        if (pos < BCAP) g_bsrc[(t * NNODES + dst) * BCAP + pos] = src;
    }

    gbar(&g_cnt1, &g_flag1, GRID1);

    // ---- phase B: thread-per-query (every 4th lane) ----
    if ((idx & 3) != 0) return;
    int qi = idx >> 2;
    if (qi >= NQ) return;
    int t = qi >> 12;
    int q = qi & (EQ - 1);
    int u = __ldg(&ei[(T_SNAP - 1) * 2 * EQ + q]);
    int v = __ldg(&ei[(T_SNAP - 1) * 2 * EQ + EQ + q]);

    int Ru[RCAP], Rv[RCAP];
    int nu = bfs2(t, u, Ru);
    int nv = bfs2(t, v, Rv);

    float t0 = 0.f, t1 = 0.f, t2 = 0.f;
#define TOP3(f) { if ((f) > t0) { t2 = t1; t1 = t0; t0 = (f); } \
                  else if ((f) > t1) { t2 = t1; t1 = (f); } \
                  else if ((f) > t2) { t2 = (f); } }

    if (nu + nv > HVY) {
        // ---- heavy fast path: local bitmaps, O(1) membership ----
        unsigned BmU[BWL], BmV[BWL];
#pragma unroll 16
        for (int i = 0; i < BWL; i++) { BmU[i] = 0u; BmV[i] = 0u; }
        for (int i = 0; i < nu; i++) BmU[Ru[i] >> 5] |= 1u << (Ru[i] & 31);
        for (int i = 0; i < nv; i++) BmV[Rv[i] >> 5] |= 1u << (Rv[i] & 31);

        for (int pass = 0; pass < 2; pass++) {
            const int* L = pass ? Rv : Ru;
            int nL = pass ? nv : nu;
            for (int i = 0; i < nL; i++) {
                int node = L[i];
                bool inRu, inRv;
                if (pass == 0) {
                    inRu = true;
                    inRv = btst(BmV, node);
                } else {
                    if (btst(BmU, node)) continue;   // handled in pass 0
                    inRu = false;
                    inRv = true;
                }
                int c = g_bcnt[t * NNODES + node];
                if (c > BCAP) c = BCAP;
                const int* b = &g_bsrc[(t * NNODES + node) * BCAP];
                int d = 0;
                for (int j = 0; j < c; j++) {
                    int src = b[j];
                    bool su = inRu && btst(BmU, src);
                    bool sv = inRv && btst(BmV, src);
                    if (su || sv) d++;
                }
                TOP3((float)d);
            }
        }
    } else {
        // ---- light path: proven cheap list scans ----
        for (int pass = 0; pass < 2; pass++) {
            const int* L = pass ? Rv : Ru;
            int nL = pass ? nv : nu;
            for (int i = 0; i < nL; i++) {
                int node = L[i];
                bool inRu, inRv;
                if (pass == 0) {
                    inRu = true;
                    inRv = in_list(Rv, nv, node);
                } else {
                    inRu = in_list(Ru, nu, node);
                    if (inRu) continue;        // handled in pass 0
                    inRv = true;
                }
                int c = g_bcnt[t * NNODES + node];
                if (c > BCAP) c = BCAP;
                const int* b = &g_bsrc[(t * NNODES + node) * BCAP];
                int d = 0;
                for (int j = 0; j < c; j++) {
                    int src = b[j];
                    bool su = inRu && in_list(Ru, nu, src);
                    bool sv = inRv && in_list(Rv, nv, src);
                    if (su || sv) d++;
                }
                TOP3((float)d);
            }
        }
    }
#undef TOP3
    g_tops[qi * 3 + 0] = t0;
    g_tops[qi * 3 + 1] = t1;
    g_tops[qi * 3 + 2] = t2;
}

// ---------------------------------------------------------------------------
// k2 (R6 verbatim, GRID2=148): gi table + 2-level dedup -> bar -> GRU -> bar
//                              -> gather
__global__ void __launch_bounds__(BLK2, 2)
k_rnn(const float* __restrict__ Wg,  const float* __restrict__ bg,
      const float* __restrict__ Wih, const float* __restrict__ Whh,
      const float* __restrict__ bih, const float* __restrict__ bhh,
      float* __restrict__ out) {
    __shared__ float sWihT[H][3 * H];   // [kk][j], conflict-free
    __shared__ float sWhhT[H][3 * H];
    __shared__ float sbhh[3 * H];
    __shared__ float sWg[H], sbg[H];
    __shared__ int   bkey[256];         // block-level dedup table
    __shared__ int   bval[256];

    int tid = threadIdx.x;
    int idx = blockIdx.x * BLK2 + tid;

    if (idx == 0) g_flag1 = 0;          // reset k1 barrier flag for next call

    for (int i = tid; i < 3 * H * H; i += BLK2) {
        int j = i / H, kk = i - j * H;
        sWihT[kk][j] = Wih[i];
        sWhhT[kk][j] = Whh[i];
    }
    if (tid < 3 * H) sbhh[tid] = bhh[tid];
    if (tid < H) { sWg[tid] = Wg[tid]; sbg[tid] = bg[tid]; }
    for (int i = tid; i < 256; i += BLK2) bkey[i] = 0;
    __syncthreads();

    // ---- phase A1: gi(v) table ----
    if (idx < 256 * 3 * H) {
        int v = idx / (3 * H);
        int j = idx - v * (3 * H);
        float acc = __ldg(&bih[j]);
        float fv = (float)v;
#pragma unroll
        for (int kk = 0; kk < H; kk++) {
            float xk = fmaxf(fv * sWg[kk] + sbg[kk], 0.f);
            acc += sWihT[kk][j] * xk;
        }
        g_gi[idx] = acc;
    }

    // ---- phase A2: two-level dedup of degree 4-tuples ----
    int  bi = -1;
    bool rep = false;
    int  key = 0;
    float v0 = 0.f, v1 = 0.f, v2 = 0.f, v3 = 0.f;
    for (int b = idx; b < NB; b += NTH2) {
        int q = b / 3, p = b - q * 3;
        v0 = g_tops[(0 * EQ + q) * 3 + p];
        v1 = g_tops[(1 * EQ + q) * 3 + p];
        v2 = g_tops[(2 * EQ + q) * 3 + p];
        v3 = g_tops[(3 * EQ + q) * 3 + p];
        int i0 = (int)v0, i1 = (int)v1, i2 = (int)v2, i3 = (int)v3;
        if (i0 > 254 || i1 > 254 || i2 > 254 || i3 > 254)
            key = (int)(0x80000000u | (unsigned)b);        // unique-self
        else
            key = i0 | (i1 << 8) | (i2 << 16) | (i3 << 24) | 0x40000000;
        unsigned p2 = ((unsigned)key * 2654435761u) & 255u;
        for (;;) {
            int old = atomicCAS(&bkey[p2], 0, key);
            if (old == 0)  { rep = true; bi = (int)p2; break; }
            if (old == key) { bi = (int)p2; break; }
            p2 = (p2 + 1) & 255u;
        }
        break;                       // NB < NTH2 * 2; at most one b per thread
    }
    __syncthreads();
    if (rep) {
        unsigned hsl = ((unsigned)key * 2654435761u) & (HT - 1);
        int slot;
        for (;;) {
            int cur = ((volatile int*)g_htkey)[hsl];
            if (cur == key) { slot = (int)hsl; break; }
            if (cur == 0) {
                int old = atomicCAS(&g_htkey[hsl], 0, key);
                if (old == 0) {
                    g_slotv[hsl] = make_float4(v0, v1, v2, v3);
                    int u = atomicAdd(&g_uniq_cnt, 1);
                    g_uniq[u] = (int)hsl;
                    slot = (int)hsl;
                    break;
                }
                if (old == key) { slot = (int)hsl; break; }
            }
            hsl = (hsl + 1) & (HT - 1);
        }
        bval[bi] = slot;
    }
    __syncthreads();
    if (idx < NB) g_bslot[idx] = bval[bi];

    gbar(&g_cnt2, &g_flag2, GRID2);

    // ---- phase B1: clear bucket counters for next call ----
    for (int i = idx; i < T_SNAP * NNODES; i += NTH2) g_bcnt[i] = 0;

    // ---- phase B2: GRU per unique trajectory (one warp each) ----
    int cnt = g_uniq_cnt;
    int lane = tid & 31;
    int w = blockIdx.x * (BLK2 / 32) + (tid >> 5);
    for (int wg = w; wg < cnt; wg += NWARP2) {
        int slot = g_uniq[wg];
        float4 vv = g_slotv[slot];
        float vs[4] = {vv.x, vv.y, vv.z, vv.w};

        float pr[4], pz[4], pg[4];
#pragma unroll
        for (int t = 0; t < T_SNAP; t++) {
            int iv = (int)vs[t];
            if (iv >= 0 && iv < 256) {
                const float* gp = &g_gi[iv * 3 * H];
                pr[t] = gp[lane];
                pz[t] = gp[H + lane];
                pg[t] = gp[2 * H + lane];
            } else {   // rare exact fallback
                float x = fmaxf(vs[t] * sWg[lane] + sbg[lane], 0.f);
                float ar = __ldg(&bih[lane]);
                float az = __ldg(&bih[H + lane]);
                float ag = __ldg(&bih[2 * H + lane]);
                for (int kk = 0; kk < H; kk++) {
                    float xk = __shfl_sync(0xffffffffu, x, kk);
                    ar += sWihT[kk][lane]         * xk;
                    az += sWihT[kk][H + lane]     * xk;
                    ag += sWihT[kk][2 * H + lane] * xk;
                }
                pr[t] = ar; pz[t] = az; pg[t] = ag;
            }
        }

        float h = 0.f;
#pragma unroll
        for (int t = 0; t < T_SNAP; t++) {
            float hr = sbhh[lane], hz = sbhh[H + lane], hg = sbhh[2 * H + lane];
#pragma unroll
            for (int kk = 0; kk < H; kk++) {
                float hk = __shfl_sync(0xffffffffu, h, kk);
                hr += sWhhT[kk][lane]         * hk;
                hz += sWhhT[kk][H + lane]     * hk;
                hg += sWhhT[kk][2 * H + lane] * hk;
            }
            float r = fast_sigmoid(pr[t] + hr);
            float z = fast_sigmoid(pz[t] + hz);
            float n = fast_tanh(pg[t] + r * hg);
            h = (1.f - z) * n + z * h;
        }
        g_uh[slot * H + lane] = h;
        if (lane == 0) g_htkey[slot] = 0;   // reset for next call
    }

    gbar(&g_cnt3, &g_flag3, GRID2);

    // ---- phase C: parallel coalesced gather to output ----
    for (int i = idx; i < NB * H; i += NTH2) {
        int b = i >> 5;
        int j = i & (H - 1);
        out[i] = g_uh[g_bslot[b] * H + j];
    }
}

// ---------------------------------------------------------------------------
extern "C" void kernel_launch(void* const* d_in, const int* in_sizes, int n_in,
                              void* d_out, int out_size) {
    const int*   ei  = (const int*)d_in[0];
    const float* Wg  = (const float*)d_in[1];
    const float* bg  = (const float*)d_in[2];
    const float* Wih = (const float*)d_in[3];
    const float* Whh = (const float*)d_in[4];
    const float* bih = (const float*)d_in[5];
    const float* bhh = (const float*)d_in[6];
    float* out = (float*)d_out;

    k_graph<<<GRID1, BLK1>>>(ei);
    k_rnn  <<<GRID2, BLK2>>>(Wg, bg, Wih, Whh, bih, bhh, out);
}